// round 3
// baseline (speedup 1.0000x reference)
#include <cuda_runtime.h>
#include <cstdint>

#define NUM_HASHES   8
#define NUM_BUCKETS  16384
#define SHARD        96
#define HIDDEN       768
#define BATCH        8
#define SEQ          8192
#define TOKENS       (BATCH * SEQ)
#define LN_EPS       1e-6f

// float4 units
#define SHARD_V4     (SHARD / 4)                 // 24
#define TABLE_V4     (NUM_BUCKETS * SHARD_V4)    // float4 stride per hash table
#define HIDDEN_V4    (HIDDEN / 4)                // 192

__global__ __launch_bounds__(256, 8)
void canine_emb_ln_kernel(const int* __restrict__ ids,
                          const float4* __restrict__ tables,
                          const float4* __restrict__ ln_scale,
                          const float4* __restrict__ ln_bias,
                          float4* __restrict__ out)
{
    const int warp = (blockIdx.x * blockDim.x + threadIdx.x) >> 5;
    const int lane = threadIdx.x & 31;
    if (warp >= TOKENS) return;

    // hash: ((id + 1) * prime) % 16384  — exact in uint32 wrap-arithmetic
    // (id < 1114112, so (id+1)*113 < 2^27 — no overflow at all)
    const unsigned idp1 = (unsigned)ids[warp] + 1u;

    const int primes[NUM_HASHES] = {31, 43, 59, 61, 73, 97, 103, 113};
    int rowbase[NUM_HASHES];  // float4 index of each gathered row start
#pragma unroll
    for (int h = 0; h < NUM_HASHES; h++) {
        unsigned b = (idp1 * (unsigned)primes[h]) & (NUM_BUCKETS - 1);
        rowbase[h] = h * TABLE_V4 + (int)b * SHARD_V4;
    }

    // Gather 6 float4 per lane (lane-stride-1 within each i => coalesced)
    float4 v[6];
    float s = 0.f, s2 = 0.f;
#pragma unroll
    for (int i = 0; i < 6; i++) {
        int f = lane + 32 * i;           // 0..191
        int h = f / 24;                  // shard
        int c = f - h * 24;              // column (float4) within shard
        float4 t = __ldg(&tables[rowbase[h] + c]);
        v[i] = t;
        s  += t.x + t.y + t.z + t.w;
        s2 += t.x * t.x + t.y * t.y + t.z * t.z + t.w * t.w;
    }

    // warp-wide reduction
#pragma unroll
    for (int o = 16; o; o >>= 1) {
        s  += __shfl_xor_sync(0xFFFFFFFFu, s,  o);
        s2 += __shfl_xor_sync(0xFFFFFFFFu, s2, o);
    }

    const float mean = s * (1.0f / (float)HIDDEN);
    const float var  = s2 * (1.0f / (float)HIDDEN) - mean * mean;
    const float inv  = rsqrtf(var + LN_EPS);

    const int out_base = warp * HIDDEN_V4;
#pragma unroll
    for (int i = 0; i < 6; i++) {
        int f = lane + 32 * i;
        float4 g = __ldg(&ln_scale[f]);
        float4 b = __ldg(&ln_bias[f]);
        float4 t = v[i];
        float4 o;
        o.x = (t.x - mean) * inv * g.x + b.x;
        o.y = (t.y - mean) * inv * g.y + b.y;
        o.z = (t.z - mean) * inv * g.z + b.z;
        o.w = (t.w - mean) * inv * g.w + b.w;
        out[out_base + f] = o;
    }
}

extern "C" void kernel_launch(void* const* d_in, const int* in_sizes, int n_in,
                              void* d_out, int out_size)
{
    const int*    ids      = (const int*)d_in[0];
    const float4* tables   = (const float4*)d_in[1];
    const float4* ln_scale = (const float4*)d_in[2];
    const float4* ln_bias  = (const float4*)d_in[3];
    float4*       out      = (float4*)d_out;

    // one warp per token, 8 warps per block
    const int threads = 256;
    const int blocks  = TOKENS / (threads / 32);  // 8192
    canine_emb_ln_kernel<<<blocks, threads>>>(ids, tables, ln_scale, ln_bias, out);
}

// round 7
// speedup vs baseline: 1.1855x; 1.1855x over previous
#include <cuda_runtime.h>
#include <cstdint>

#define NUM_HASHES   8
#define NUM_BUCKETS  16384
#define SHARD        96
#define HIDDEN       768
#define BATCH        8
#define SEQ          8192
#define TOKENS       (BATCH * SEQ)
#define LN_EPS       1e-6f

// float4 units
#define SHARD_V4     (SHARD / 4)                 // 24
#define TABLE_V4     (NUM_BUCKETS * SHARD_V4)    // float4 stride per hash table
#define HIDDEN_V4    (HIDDEN / 4)                // 192

// Table gather: non-coherent load with an evict_last cache policy operand
// (the bare .L2::evict_last modifier is only legal on 256-bit loads on sm_100a;
//  the createpolicy + .L2::cache_hint form works for .v4.f32).
__device__ __forceinline__ float4 ldg_table(const float4* p, uint64_t pol) {
    float4 v;
    asm volatile("ld.global.nc.L2::cache_hint.v4.f32 {%0,%1,%2,%3}, [%4], %5;"
                 : "=f"(v.x), "=f"(v.y), "=f"(v.z), "=f"(v.w)
                 : "l"(p), "l"(pol));
    return v;
}

// Output store: streaming (evict-first) — never re-read, keep it out of L2.
__device__ __forceinline__ void st_stream(float4* p, float4 v) {
    asm volatile("st.global.cs.v4.f32 [%0], {%1,%2,%3,%4};"
                 :: "l"(p), "f"(v.x), "f"(v.y), "f"(v.z), "f"(v.w));
}

__global__ __launch_bounds__(256, 8)
void canine_emb_ln_kernel(const int* __restrict__ ids,
                          const float4* __restrict__ tables,
                          const float4* __restrict__ ln_scale,
                          const float4* __restrict__ ln_bias,
                          float4* __restrict__ out)
{
    const int warp = (blockIdx.x * blockDim.x + threadIdx.x) >> 5;
    const int lane = threadIdx.x & 31;
    if (warp >= TOKENS) return;

    // evict_last policy for the table working set (fraction = 1.0)
    uint64_t pol;
    asm volatile("createpolicy.fractional.L2::evict_last.b64 %0, 1.0;" : "=l"(pol));

    // hash: ((id + 1) * prime) % 16384 — exact in uint32 (ids < 2^21)
    const unsigned idp1 = (unsigned)ids[warp] + 1u;

    const int primes[NUM_HASHES] = {31, 43, 59, 61, 73, 97, 103, 113};
    int rowbase[NUM_HASHES];  // float4 index of each gathered row start
#pragma unroll
    for (int h = 0; h < NUM_HASHES; h++) {
        unsigned b = (idp1 * (unsigned)primes[h]) & (NUM_BUCKETS - 1);
        rowbase[h] = h * TABLE_V4 + (int)b * SHARD_V4;
    }

    // Gather 6 float4 per lane (lane-stride-1 within each i => coalesced)
    float4 v[6];
    float s = 0.f, s2 = 0.f;
#pragma unroll
    for (int i = 0; i < 6; i++) {
        int f = lane + 32 * i;           // 0..191
        int h = f / 24;                  // shard
        int c = f - h * 24;              // column (float4) within shard
        float4 t = ldg_table(&tables[rowbase[h] + c], pol);
        v[i] = t;
        s  += t.x + t.y + t.z + t.w;
        s2 += t.x * t.x + t.y * t.y + t.z * t.z + t.w * t.w;
    }

    // warp-wide reduction
#pragma unroll
    for (int o = 16; o; o >>= 1) {
        s  += __shfl_xor_sync(0xFFFFFFFFu, s,  o);
        s2 += __shfl_xor_sync(0xFFFFFFFFu, s2, o);
    }

    const float mean = s * (1.0f / (float)HIDDEN);
    const float var  = s2 * (1.0f / (float)HIDDEN) - mean * mean;
    const float inv  = rsqrtf(var + LN_EPS);

    const int out_base = warp * HIDDEN_V4;
#pragma unroll
    for (int i = 0; i < 6; i++) {
        int f = lane + 32 * i;
        float4 g = __ldg(&ln_scale[f]);
        float4 b = __ldg(&ln_bias[f]);
        float4 t = v[i];
        float4 o;
        o.x = (t.x - mean) * inv * g.x + b.x;
        o.y = (t.y - mean) * inv * g.y + b.y;
        o.z = (t.z - mean) * inv * g.z + b.z;
        o.w = (t.w - mean) * inv * g.w + b.w;
        st_stream(&out[out_base + f], o);
    }
}

extern "C" void kernel_launch(void* const* d_in, const int* in_sizes, int n_in,
                              void* d_out, int out_size)
{
    const int*    ids      = (const int*)d_in[0];
    const float4* tables   = (const float4*)d_in[1];
    const float4* ln_scale = (const float4*)d_in[2];
    const float4* ln_bias  = (const float4*)d_in[3];
    float4*       out      = (float4*)d_out;

    // one warp per token, 8 warps per block
    const int threads = 256;
    const int blocks  = TOKENS / (threads / 32);  // 8192
    canine_emb_ln_kernel<<<blocks, threads>>>(ids, tables, ln_scale, ln_bias, out);
}